// round 5
// baseline (speedup 1.0000x reference)
#include <cuda_runtime.h>

// HardwareVMMoperation: out = sum_{c<32} Q(x[:,128c:128c+128] @ W[:,128c:128c+128]^T) + bias
// x: [B, K] fp32, W: [N, K] fp32, bias: [N] fp32, out: [B, N] fp32
// B=8192, K=N=4096 (B derived from in_sizes).
// Q(p) = rint(clamp(p,-2.56,2.56) * 255/2.56) * (2.56/255), round-half-even.

#define K_DIM  4096
#define N_DIM  4096
#define BM     128
#define BN     128
#define KS     16          // k per substep
#define THREADS 256
#define NSUB   (K_DIM / KS)   // 256 substeps
#define SUB_PER_CHUNK 8       // 128 / 16

__device__ __forceinline__ unsigned long long dup2(float v) {
    unsigned long long r;
    asm("mov.b64 %0, {%1, %1};" : "=l"(r) : "f"(v));
    return r;
}

__device__ __forceinline__ void ffma2(unsigned long long &d,
                                      unsigned long long a,
                                      unsigned long long b) {
    asm("fma.rn.f32x2 %0, %1, %2, %0;" : "+l"(d) : "l"(a), "l"(b));
}

__device__ __forceinline__ float2 unpack2(unsigned long long v) {
    float2 f;
    asm("mov.b64 {%0, %1}, %2;" : "=f"(f.x), "=f"(f.y) : "l"(v));
    return f;
}

__device__ __forceinline__ float quantize_partial(float p) {
    float y = fminf(fmaxf(p, -2.56f), 2.56f);
    y = y * (255.0f / 2.56f);   // 99.609375, exactly representable
    y = rintf(y);               // round half to even == jnp.round
    return y * (2.56f / 255.0f);
}

__global__ void __launch_bounds__(THREADS, 1)
vmm_quant_kernel(const float* __restrict__ x,
                 const float* __restrict__ w,
                 const float* __restrict__ bias,
                 float* __restrict__ out) {
    // k-major smem tiles (transposed on store), double buffered
    __shared__ __align__(16) float As[2][KS][BM];
    __shared__ __align__(16) float Bs[2][KS][BN];

    const int tid = threadIdx.x;
    const int tx  = tid & 15;   // n sub-tile
    const int ty  = tid >> 4;   // m sub-tile
    const int n0  = blockIdx.x * BN;
    const int m0  = blockIdx.y * BM;

    // loader mapping: 512 float4 per matrix per substep; 2 per thread
    const int ldr = tid >> 2;   // 0..63 (row), second row = ldr+64
    const int ldq = tid & 3;    // k-quad within substep (4 quads * 4 = 16 k)

    const float* ax = x + (size_t)(m0 + ldr) * K_DIM + ldq * 4;
    const float* bx = w + (size_t)(n0 + ldr) * K_DIM + ldq * 4;

    unsigned long long pacc[4][8];   // packed fp32x2 partial (rows 2mi, 2mi+1)
    float racc[8][8];                // running quantized accumulator
    #pragma unroll
    for (int i = 0; i < 4; ++i)
        #pragma unroll
        for (int j = 0; j < 8; ++j) pacc[i][j] = 0ULL;
    #pragma unroll
    for (int i = 0; i < 8; ++i)
        #pragma unroll
        for (int j = 0; j < 8; ++j) racc[i][j] = 0.0f;

    // ---- prologue: substep 0 -> buf 0 ----
    {
        float4 a0 = *(const float4*)(ax);
        float4 a1 = *(const float4*)(ax + (size_t)64 * K_DIM);
        float4 b0 = *(const float4*)(bx);
        float4 b1 = *(const float4*)(bx + (size_t)64 * K_DIM);
        As[0][ldq * 4 + 0][ldr]      = a0.x;
        As[0][ldq * 4 + 1][ldr]      = a0.y;
        As[0][ldq * 4 + 2][ldr]      = a0.z;
        As[0][ldq * 4 + 3][ldr]      = a0.w;
        As[0][ldq * 4 + 0][ldr + 64] = a1.x;
        As[0][ldq * 4 + 1][ldr + 64] = a1.y;
        As[0][ldq * 4 + 2][ldr + 64] = a1.z;
        As[0][ldq * 4 + 3][ldr + 64] = a1.w;
        Bs[0][ldq * 4 + 0][ldr]      = b0.x;
        Bs[0][ldq * 4 + 1][ldr]      = b0.y;
        Bs[0][ldq * 4 + 2][ldr]      = b0.z;
        Bs[0][ldq * 4 + 3][ldr]      = b0.w;
        Bs[0][ldq * 4 + 0][ldr + 64] = b1.x;
        Bs[0][ldq * 4 + 1][ldr + 64] = b1.y;
        Bs[0][ldq * 4 + 2][ldr + 64] = b1.z;
        Bs[0][ldq * 4 + 3][ldr + 64] = b1.w;
    }
    __syncthreads();

    int buf = 0;
    for (int s = 0; s < NSUB; ++s) {
        // prefetch next substep into registers (hidden under compute)
        float4 a0, a1, b0, b1;
        const bool has_next = (s + 1 < NSUB);
        if (has_next) {
            const float* ap = ax + (size_t)(s + 1) * KS;
            const float* bp = bx + (size_t)(s + 1) * KS;
            a0 = *(const float4*)(ap);
            a1 = *(const float4*)(ap + (size_t)64 * K_DIM);
            b0 = *(const float4*)(bp);
            b1 = *(const float4*)(bp + (size_t)64 * K_DIM);
        }

        // ---- compute 16 k-steps from smem[buf] ----
        #pragma unroll
        for (int kk = 0; kk < KS; ++kk) {
            ulonglong2 av0 = *(const ulonglong2*)&As[buf][kk][ty * 8];
            ulonglong2 av1 = *(const ulonglong2*)&As[buf][kk][ty * 8 + 4];
            float4 bv0 = *(const float4*)&Bs[buf][kk][tx * 8];
            float4 bv1 = *(const float4*)&Bs[buf][kk][tx * 8 + 4];

            unsigned long long am[4] = {av0.x, av0.y, av1.x, av1.y};
            unsigned long long bd[8] = {dup2(bv0.x), dup2(bv0.y), dup2(bv0.z), dup2(bv0.w),
                                        dup2(bv1.x), dup2(bv1.y), dup2(bv1.z), dup2(bv1.w)};
            #pragma unroll
            for (int mi = 0; mi < 4; ++mi)
                #pragma unroll
                for (int j = 0; j < 8; ++j)
                    ffma2(pacc[mi][j], am[mi], bd[j]);
        }

        // ---- per-128-K-chunk ADC quantization ----
        if ((s & (SUB_PER_CHUNK - 1)) == (SUB_PER_CHUNK - 1)) {
            #pragma unroll
            for (int mi = 0; mi < 4; ++mi)
                #pragma unroll
                for (int j = 0; j < 8; ++j) {
                    float2 p = unpack2(pacc[mi][j]);
                    racc[2 * mi + 0][j] += quantize_partial(p.x);
                    racc[2 * mi + 1][j] += quantize_partial(p.y);
                    pacc[mi][j] = 0ULL;
                }
        }

        // ---- stage next tile into the other buffer ----
        if (has_next) {
            const int nb = buf ^ 1;
            As[nb][ldq * 4 + 0][ldr]      = a0.x;
            As[nb][ldq * 4 + 1][ldr]      = a0.y;
            As[nb][ldq * 4 + 2][ldr]      = a0.z;
            As[nb][ldq * 4 + 3][ldr]      = a0.w;
            As[nb][ldq * 4 + 0][ldr + 64] = a1.x;
            As[nb][ldq * 4 + 1][ldr + 64] = a1.y;
            As[nb][ldq * 4 + 2][ldr + 64] = a1.z;
            As[nb][ldq * 4 + 3][ldr + 64] = a1.w;
            Bs[nb][ldq * 4 + 0][ldr]      = b0.x;
            Bs[nb][ldq * 4 + 1][ldr]      = b0.y;
            Bs[nb][ldq * 4 + 2][ldr]      = b0.z;
            Bs[nb][ldq * 4 + 3][ldr]      = b0.w;
            Bs[nb][ldq * 4 + 0][ldr + 64] = b1.x;
            Bs[nb][ldq * 4 + 1][ldr + 64] = b1.y;
            Bs[nb][ldq * 4 + 2][ldr + 64] = b1.z;
            Bs[nb][ldq * 4 + 3][ldr + 64] = b1.w;
            __syncthreads();
            buf = nb;
        }
    }

    // ---- epilogue: add bias, store ----
    const float* bptr = bias + n0 + tx * 8;
    float4 bb0 = *(const float4*)(bptr);
    float4 bb1 = *(const float4*)(bptr + 4);

    #pragma unroll
    for (int r = 0; r < 8; ++r) {
        float* op = out + (size_t)(m0 + ty * 8 + r) * N_DIM + n0 + tx * 8;
        float4 o0, o1;
        o0.x = racc[r][0] + bb0.x;
        o0.y = racc[r][1] + bb0.y;
        o0.z = racc[r][2] + bb0.z;
        o0.w = racc[r][3] + bb0.w;
        o1.x = racc[r][4] + bb1.x;
        o1.y = racc[r][5] + bb1.y;
        o1.z = racc[r][6] + bb1.z;
        o1.w = racc[r][7] + bb1.w;
        *(float4*)(op)     = o0;
        *(float4*)(op + 4) = o1;
    }
}

extern "C" void kernel_launch(void* const* d_in, const int* in_sizes, int n_in,
                              void* d_out, int out_size) {
    const float* x    = (const float*)d_in[0];
    const float* w    = (const float*)d_in[1];
    const float* bias = (const float*)d_in[2];
    float* out = (float*)d_out;

    const int Bdim = in_sizes[0] / K_DIM;   // 8192
    dim3 grid(N_DIM / BN, Bdim / BM);       // (32, 64)
    vmm_quant_kernel<<<grid, THREADS>>>(x, w, bias, out);
}

// round 7
// speedup vs baseline: 10.3232x; 10.3232x over previous
#include <cuda_runtime.h>
#include <cuda_bf16.h>
#include <cstdint>

// ============================================================================
// HardwareVMMoperation: out = sum_{c<32} Q(x[:,128c:+128] @ W[:,128c:+128]^T) + bias
// B=8192, K=N=4096 fp32.  Q = clamp(+-2.56) -> *(255/2.56) -> rint -> back.
//
// Two device-code variants selected per compilation pass:
//   - sm_103a pass (__CUDA_ARCH_FEAT_SM103_ALL): tcgen05 bf16 3-term split GEMM
//   - plain sm_103 / compute_103 pass: FFMA2 SIMT fallback (known-correct)
// Host launch config is identical for both.
// ============================================================================

#if defined(__CUDA_ARCH__) && defined(__CUDA_ARCH_FEAT_SM103_ALL)
#define TC_ON 1
#else
#define TC_ON 0
#endif

#define K_DIM   4096
#define N_DIM   4096
#define BM      128
#define BN      128
#define KSUB    64
#define NSTAGE  3
#define TILE_BYTES  16384          // 128 rows x 64 bf16, SW128-swizzled image
#define STAGE_BYTES 65536          // Ah, Al, Bh, Bl
#define NSS     (K_DIM / KSUB)     // 64
#define NCHUNK  32
#define THREADS 320                // 8 epi + 1 mma + 1 producer warps
#define MMA_WARP  8
#define PROD_WARP 9
#define IDESC   0x8200490u
#define DYN_BYTES (NSTAGE * STAGE_BYTES + 1024)

#define MB_TILES (8192 / BM)       // 64
#define KB_TILES (K_DIM / KSUB)    // 64

// packed hi/lo bf16 scratch (device globals = allowed scratch path)
__device__ __align__(128) uint8_t g_xpack[(size_t)MB_TILES * KB_TILES * 2 * TILE_BYTES];
__device__ __align__(128) uint8_t g_wpack[(size_t)(N_DIM / BN) * KB_TILES * 2 * TILE_BYTES];

// ---------------------------------------------------------------------------
// arch-independent helpers
// ---------------------------------------------------------------------------
__device__ __forceinline__ float quantize_partial(float p) {
    float y = fminf(fmaxf(p, -2.56f), 2.56f);
    y = y * (255.0f / 2.56f);   // 99.609375 exact
    y = rintf(y);               // round half to even
    return y * (2.56f / 255.0f);
}

__device__ __forceinline__ uint32_t smem_u32(const void* p) {
    return (uint32_t)__cvta_generic_to_shared(p);
}

#if TC_ON
// ---------------------------------------------------------------------------
// sm_103a-only helpers
// ---------------------------------------------------------------------------
__device__ __forceinline__ bool elect_one() {
    uint32_t p;
    asm volatile("{\n\t.reg .pred P;\n\telect.sync _|P, 0xFFFFFFFF;\n\t"
                 "selp.b32 %0, 1, 0, P;\n\t}" : "=r"(p));
    return p != 0;
}
__device__ __forceinline__ void mbar_init(uint32_t bar, uint32_t cnt) {
    asm volatile("mbarrier.init.shared.b64 [%0], %1;" :: "r"(bar), "r"(cnt) : "memory");
}
__device__ __forceinline__ void mbar_expect_tx(uint32_t bar, uint32_t bytes) {
    asm volatile("mbarrier.arrive.expect_tx.shared.b64 _, [%0], %1;"
                 :: "r"(bar), "r"(bytes) : "memory");
}
__device__ __forceinline__ void mbar_arrive(uint32_t bar) {
    asm volatile("mbarrier.arrive.shared.b64 _, [%0];" :: "r"(bar) : "memory");
}
__device__ __forceinline__ void mbar_wait(uint32_t bar, uint32_t parity) {
    asm volatile("{\n\t.reg .pred P;\n"
        "WL%=:\n\t"
        "mbarrier.try_wait.parity.acquire.cta.shared::cta.b64 P, [%0], %1, 0x989680;\n\t"
        "@P bra WD%=;\n\t"
        "bra WL%=;\n"
        "WD%=:\n\t}"
        :: "r"(bar), "r"(parity) : "memory");
}
__device__ __forceinline__ void bulk_cp(uint32_t dst, const void* src, uint32_t bytes,
                                        uint32_t bar) {
    asm volatile("cp.async.bulk.shared::cluster.global.mbarrier::complete_tx::bytes "
                 "[%0], [%1], %2, [%3];"
                 :: "r"(dst), "l"(src), "r"(bytes), "r"(bar) : "memory");
}
__device__ __forceinline__ uint64_t make_desc(uint32_t addr) {
    const uint64_t base = (2ULL << 61) | (1ULL << 46) | (64ULL << 32) | (1ULL << 16);
    return base | (uint64_t)((addr >> 4) & 0x3FFF);
}
__device__ __forceinline__ void mma_ss(uint32_t d, uint64_t a, uint64_t b, uint32_t en) {
    asm volatile("{\n\t.reg .pred p;\n\tsetp.ne.u32 p, %4, 0;\n\t"
        "tcgen05.mma.cta_group::1.kind::f16 [%0], %1, %2, %3, {%5, %5, %5, %5}, p;\n\t}"
        :: "r"(d), "l"(a), "l"(b), "r"(IDESC), "r"(en), "r"(0u) : "memory");
}
__device__ __forceinline__ void tc_commit(uint32_t bar) {
    asm volatile("tcgen05.commit.cta_group::1.mbarrier::arrive::one.shared::cluster.b64 [%0];"
                 :: "r"(bar) : "memory");
}
__device__ __forceinline__ void ldtm16(uint32_t* r, uint32_t addr) {
    asm volatile("tcgen05.ld.sync.aligned.32x32b.x16.b32 "
        "{%0,%1,%2,%3,%4,%5,%6,%7,%8,%9,%10,%11,%12,%13,%14,%15}, [%16];"
        : "=r"(r[0]), "=r"(r[1]), "=r"(r[2]), "=r"(r[3]),
          "=r"(r[4]), "=r"(r[5]), "=r"(r[6]), "=r"(r[7]),
          "=r"(r[8]), "=r"(r[9]), "=r"(r[10]), "=r"(r[11]),
          "=r"(r[12]), "=r"(r[13]), "=r"(r[14]), "=r"(r[15])
        : "r"(addr));
}
__device__ __forceinline__ void tc_wait_ld()      { asm volatile("tcgen05.wait::ld.sync.aligned;" ::: "memory"); }
__device__ __forceinline__ void tc_fence_before() { asm volatile("tcgen05.fence::before_thread_sync;" ::: "memory"); }
__device__ __forceinline__ void tc_fence_after()  { asm volatile("tcgen05.fence::after_thread_sync;" ::: "memory"); }
#else
// FFMA2 helpers for fallback
__device__ __forceinline__ unsigned long long dup2(float v) {
    unsigned long long r;
    asm("mov.b64 %0, {%1, %1};" : "=l"(r) : "f"(v));
    return r;
}
__device__ __forceinline__ void ffma2(unsigned long long &d,
                                      unsigned long long a, unsigned long long b) {
    asm("fma.rn.f32x2 %0, %1, %2, %0;" : "+l"(d) : "l"(a), "l"(b));
}
__device__ __forceinline__ float2 unpack2(unsigned long long v) {
    float2 f;
    asm("mov.b64 {%0, %1}, %2;" : "=f"(f.x), "=f"(f.y) : "l"(v));
    return f;
}
#endif

// ---------------------------------------------------------------------------
// Pre-pass: fp32 [rows,4096] -> hi/lo bf16, SW128-swizzled 128x64 tiles.
// (no-op on the fallback arch; fallback reads fp32 directly)
// ---------------------------------------------------------------------------
__global__ void __launch_bounds__(256)
pack_kernel(const float* __restrict__ src, uint8_t* __restrict__ dst, int rows) {
#if TC_ON
    int idx = blockIdx.x * blockDim.x + threadIdx.x;   // one thread = 8 k's
    int kq  = idx & (K_DIM / 8 - 1);
    int row = idx >> 9;
    if (row >= rows) return;

    const float4* s = (const float4*)(src + (size_t)row * K_DIM + kq * 8);
    float4 v0 = s[0], v1 = s[1];
    float f[8] = {v0.x, v0.y, v0.z, v0.w, v1.x, v1.y, v1.z, v1.w};

    uint32_t hi[4], lo[4];
#pragma unroll
    for (int i = 0; i < 4; ++i) {
        __nv_bfloat16 h0 = __float2bfloat16_rn(f[2 * i]);
        __nv_bfloat16 h1 = __float2bfloat16_rn(f[2 * i + 1]);
        __nv_bfloat16 l0 = __float2bfloat16_rn(f[2 * i]     - __bfloat162float(h0));
        __nv_bfloat16 l1 = __float2bfloat16_rn(f[2 * i + 1] - __bfloat162float(h1));
        hi[i] = (uint32_t)__bfloat16_as_ushort(h0) | ((uint32_t)__bfloat16_as_ushort(h1) << 16);
        lo[i] = (uint32_t)__bfloat16_as_ushort(l0) | ((uint32_t)__bfloat16_as_ushort(l1) << 16);
    }

    int rb = row >> 7, r = row & 127;
    int k  = kq * 8;
    int kb = k >> 6, c = k & 63;
    uint32_t off = (uint32_t)(r * 128 + c * 2);
    off ^= (off >> 3) & 0x70;
    size_t tbase = ((size_t)(rb * KB_TILES + kb)) * (2 * TILE_BYTES);
    *(uint4*)(dst + tbase + off)              = make_uint4(hi[0], hi[1], hi[2], hi[3]);
    *(uint4*)(dst + tbase + TILE_BYTES + off) = make_uint4(lo[0], lo[1], lo[2], lo[3]);
#else
    (void)src; (void)dst; (void)rows;
#endif
}

// ---------------------------------------------------------------------------
// Main kernel (arch-variant body, unified launch config: grid(32,64), 320 thr,
// DYN_BYTES dynamic smem)
// ---------------------------------------------------------------------------
__global__ void __launch_bounds__(THREADS, 1)
vmm_main_kernel(const float* __restrict__ x, const float* __restrict__ w,
                const float* __restrict__ bias, float* __restrict__ out) {
    extern __shared__ uint8_t dyn[];
#if TC_ON
    // ======================= tcgen05 path =======================
    __shared__ __align__(8) uint64_t s_full[NSTAGE], s_empty[NSTAGE];
    __shared__ __align__(8) uint64_t s_mma_done[2], s_epi_done[2];
    __shared__ uint32_t s_tmem_ptr;

    const uint32_t sbase = (smem_u32(dyn) + 1023) & ~1023u;
    const int tid  = threadIdx.x;
    const int wid  = tid >> 5;
    const int lane = tid & 31;
    const int nblk = blockIdx.x, mblk = blockIdx.y;
    const int n0 = nblk * BN, m0 = mblk * BM;

    if (tid == 0) {
#pragma unroll
        for (int s = 0; s < NSTAGE; ++s) {
            mbar_init(smem_u32(&s_full[s]), 1);
            mbar_init(smem_u32(&s_empty[s]), 1);
        }
        mbar_init(smem_u32(&s_mma_done[0]), 1);
        mbar_init(smem_u32(&s_mma_done[1]), 1);
        mbar_init(smem_u32(&s_epi_done[0]), 256);
        mbar_init(smem_u32(&s_epi_done[1]), 256);
    }
    if (wid == MMA_WARP) {
        asm volatile("tcgen05.alloc.cta_group::1.sync.aligned.shared::cta.b32 [%0], %1;"
                     :: "r"(smem_u32(&s_tmem_ptr)), "r"(256u) : "memory");
    }
    __syncthreads();
    const uint32_t tmem = s_tmem_ptr;

    if (wid == PROD_WARP) {
        if (elect_one()) {
            const uint8_t* asrc = g_xpack + (size_t)mblk * KB_TILES * (2 * TILE_BYTES);
            const uint8_t* bsrc = g_wpack + (size_t)nblk * KB_TILES * (2 * TILE_BYTES);
            int eph[NSTAGE] = {1, 1, 1};
            for (int s = 0; s < NSS; ++s) {
                int st = s % NSTAGE;
                mbar_wait(smem_u32(&s_empty[st]), eph[st]); eph[st] ^= 1;
                uint32_t dstA = sbase + st * STAGE_BYTES;
                uint32_t fb = smem_u32(&s_full[st]);
                mbar_expect_tx(fb, STAGE_BYTES);
                bulk_cp(dstA,                  asrc + (size_t)s * (2 * TILE_BYTES), 2 * TILE_BYTES, fb);
                bulk_cp(dstA + 2 * TILE_BYTES, bsrc + (size_t)s * (2 * TILE_BYTES), 2 * TILE_BYTES, fb);
            }
        }
    } else if (wid == MMA_WARP) {
        if (elect_one()) {
            int fph[NSTAGE] = {0, 0, 0};
            int eph[2] = {1, 1};
            int st = 0;
            for (int c = 0; c < NCHUNK; ++c) {
                int slot = c & 1;
                mbar_wait(smem_u32(&s_epi_done[slot]), eph[slot]); eph[slot] ^= 1;
                tc_fence_after();
                uint32_t d = tmem + slot * 128;
                for (int sub = 0; sub < 2; ++sub) {
                    mbar_wait(smem_u32(&s_full[st]), fph[st]); fph[st] ^= 1;
                    uint32_t a = sbase + st * STAGE_BYTES;
                    uint64_t aH = make_desc(a);
                    uint64_t aL = make_desc(a + TILE_BYTES);
                    uint64_t bH = make_desc(a + 2 * TILE_BYTES);
                    uint64_t bL = make_desc(a + 3 * TILE_BYTES);
                    uint64_t ta[3] = {aH, aL, aH};
                    uint64_t tb[3] = {bH, bH, bL};
#pragma unroll
                    for (int t = 0; t < 3; ++t)
#pragma unroll
                        for (int ks = 0; ks < 4; ++ks) {
                            uint32_t en = !(sub == 0 && t == 0 && ks == 0);
                            mma_ss(d, ta[t] + ks * 2, tb[t] + ks * 2, en);
                        }
                    tc_commit(smem_u32(&s_empty[st]));   // stage free when these MMAs drain
                    st = (st + 1 == NSTAGE) ? 0 : st + 1;
                }
                tc_commit(smem_u32(&s_mma_done[slot]));  // chunk D ready
            }
        }
    } else {
        // epilogue warps 0..7: LDTM ping-pong, quantize, accumulate in regs
        const int grp = wid >> 2;        // column half
        float racc[64];
#pragma unroll
        for (int i = 0; i < 64; ++i) racc[i] = 0.0f;

        int mph[2] = {0, 0};
        for (int c = 0; c < NCHUNK; ++c) {
            int slot = c & 1;
            mbar_wait(smem_u32(&s_mma_done[slot]), mph[slot]); mph[slot] ^= 1;
            tc_fence_after();
            uint32_t base = tmem + slot * 128 + grp * 64;
#pragma unroll
            for (int b = 0; b < 4; ++b) {
                uint32_t dr[16];
                ldtm16(dr, base + b * 16);
                tc_wait_ld();
#pragma unroll
                for (int j = 0; j < 16; ++j)
                    racc[b * 16 + j] += quantize_partial(__uint_as_float(dr[j]));
            }
            tc_fence_before();
            mbar_arrive(smem_u32(&s_epi_done[slot]));
        }

        const int sp = wid & 3;          // subpartition = rows (wid%4)*32..+31
        const int m  = m0 + sp * 32 + lane;
        const float* bp = bias + n0 + grp * 64;
        float* op = out + (size_t)m * N_DIM + n0 + grp * 64;
#pragma unroll
        for (int q = 0; q < 16; ++q) {
            float4 bb = *(const float4*)(bp + q * 4);
            float4 o;
            o.x = racc[q * 4 + 0] + bb.x;
            o.y = racc[q * 4 + 1] + bb.y;
            o.z = racc[q * 4 + 2] + bb.z;
            o.w = racc[q * 4 + 3] + bb.w;
            *(float4*)(op + q * 4) = o;
        }
    }

    __syncthreads();
    if (wid == MMA_WARP) {
        asm volatile("tcgen05.relinquish_alloc_permit.cta_group::1.sync.aligned;");
        asm volatile("tcgen05.dealloc.cta_group::1.sync.aligned.b32 %0, %1;"
                     :: "r"(tmem), "r"(256u));
    }
#else
    // ======================= FFMA2 fallback (plain sm_103) =======================
    // tiles live in dynamic smem: As[2][16][128], Bs[2][16][128]
    float* As = (float*)dyn;
    float* Bs = As + 2 * 16 * 128;
#define ASF(b, k, r) As[((b) * 16 + (k)) * 128 + (r)]
#define BSF(b, k, r) Bs[((b) * 16 + (k)) * 128 + (r)]

    const int tid = threadIdx.x;
    const bool act = tid < 256;
    const int tx  = tid & 15;
    const int ty  = (tid >> 4) & 15;
    const int n0  = blockIdx.x * BN;
    const int m0  = blockIdx.y * BM;
    const int ldr = (tid >> 2) & 63;
    const int ldq = tid & 3;

    const float* ax = x + (size_t)(m0 + ldr) * K_DIM + ldq * 4;
    const float* bx = w + (size_t)(n0 + ldr) * K_DIM + ldq * 4;

    unsigned long long pacc[4][8];
    float racc[8][8];
#pragma unroll
    for (int i = 0; i < 4; ++i)
#pragma unroll
        for (int j = 0; j < 8; ++j) pacc[i][j] = 0ULL;
#pragma unroll
    for (int i = 0; i < 8; ++i)
#pragma unroll
        for (int j = 0; j < 8; ++j) racc[i][j] = 0.0f;

    if (act) {
        float4 a0 = *(const float4*)(ax);
        float4 a1 = *(const float4*)(ax + (size_t)64 * K_DIM);
        float4 b0 = *(const float4*)(bx);
        float4 b1 = *(const float4*)(bx + (size_t)64 * K_DIM);
        ASF(0, ldq * 4 + 0, ldr) = a0.x;  ASF(0, ldq * 4 + 1, ldr) = a0.y;
        ASF(0, ldq * 4 + 2, ldr) = a0.z;  ASF(0, ldq * 4 + 3, ldr) = a0.w;
        ASF(0, ldq * 4 + 0, ldr + 64) = a1.x;  ASF(0, ldq * 4 + 1, ldr + 64) = a1.y;
        ASF(0, ldq * 4 + 2, ldr + 64) = a1.z;  ASF(0, ldq * 4 + 3, ldr + 64) = a1.w;
        BSF(0, ldq * 4 + 0, ldr) = b0.x;  BSF(0, ldq * 4 + 1, ldr) = b0.y;
        BSF(0, ldq * 4 + 2, ldr) = b0.z;  BSF(0, ldq * 4 + 3, ldr) = b0.w;
        BSF(0, ldq * 4 + 0, ldr + 64) = b1.x;  BSF(0, ldq * 4 + 1, ldr + 64) = b1.y;
        BSF(0, ldq * 4 + 2, ldr + 64) = b1.z;  BSF(0, ldq * 4 + 3, ldr + 64) = b1.w;
    }
    __syncthreads();

    int buf = 0;
    const int NSUB_F = K_DIM / 16;
    for (int s = 0; s < NSUB_F; ++s) {
        float4 a0, a1, b0, b1;
        const bool has_next = (s + 1 < NSUB_F);
        if (act && has_next) {
            const float* ap = ax + (size_t)(s + 1) * 16;
            const float* bp = bx + (size_t)(s + 1) * 16;
            a0 = *(const float4*)(ap);
            a1 = *(const float4*)(ap + (size_t)64 * K_DIM);
            b0 = *(const float4*)(bp);
            b1 = *(const float4*)(bp + (size_t)64 * K_DIM);
        }

        if (act) {
#pragma unroll
            for (int kk = 0; kk < 16; ++kk) {
                ulonglong2 av0 = *(const ulonglong2*)&ASF(buf, kk, ty * 8);
                ulonglong2 av1 = *(const ulonglong2*)&ASF(buf, kk, ty * 8 + 4);
                float4 bv0 = *(const float4*)&BSF(buf, kk, tx * 8);
                float4 bv1 = *(const float4*)&BSF(buf, kk, tx * 8 + 4);
                unsigned long long am[4] = {av0.x, av0.y, av1.x, av1.y};
                unsigned long long bd[8] = {dup2(bv0.x), dup2(bv0.y), dup2(bv0.z), dup2(bv0.w),
                                            dup2(bv1.x), dup2(bv1.y), dup2(bv1.z), dup2(bv1.w)};
#pragma unroll
                for (int mi = 0; mi < 4; ++mi)
#pragma unroll
                    for (int j = 0; j < 8; ++j)
                        ffma2(pacc[mi][j], am[mi], bd[j]);
            }

            if ((s & 7) == 7) {
#pragma unroll
                for (int mi = 0; mi < 4; ++mi)
#pragma unroll
                    for (int j = 0; j < 8; ++j) {
                        float2 p = unpack2(pacc[mi][j]);
                        racc[2 * mi + 0][j] += quantize_partial(p.x);
                        racc[2 * mi + 1][j] += quantize_partial(p.y);
                        pacc[mi][j] = 0ULL;
                    }
            }
        }

        if (has_next) {
            const int nb = buf ^ 1;
            if (act) {
                ASF(nb, ldq * 4 + 0, ldr) = a0.x;  ASF(nb, ldq * 4 + 1, ldr) = a0.y;
                ASF(nb, ldq * 4 + 2, ldr) = a0.z;  ASF(nb, ldq * 4 + 3, ldr) = a0.w;
                ASF(nb, ldq * 4 + 0, ldr + 64) = a1.x;  ASF(nb, ldq * 4 + 1, ldr + 64) = a1.y;
                ASF(nb, ldq * 4 + 2, ldr + 64) = a1.z;  ASF(nb, ldq * 4 + 3, ldr + 64) = a1.w;
                BSF(nb, ldq * 4 + 0, ldr) = b0.x;  BSF(nb, ldq * 4 + 1, ldr) = b0.y;
                BSF(nb, ldq * 4 + 2, ldr) = b0.z;  BSF(nb, ldq * 4 + 3, ldr) = b0.w;
                BSF(nb, ldq * 4 + 0, ldr + 64) = b1.x;  BSF(nb, ldq * 4 + 1, ldr + 64) = b1.y;
                BSF(nb, ldq * 4 + 2, ldr + 64) = b1.z;  BSF(nb, ldq * 4 + 3, ldr + 64) = b1.w;
            }
            __syncthreads();
            buf = nb;
        }
    }

    if (act) {
        const float* bptr = bias + n0 + tx * 8;
        float4 bb0 = *(const float4*)(bptr);
        float4 bb1 = *(const float4*)(bptr + 4);
#pragma unroll
        for (int r = 0; r < 8; ++r) {
            float* op = out + (size_t)(m0 + ty * 8 + r) * N_DIM + n0 + tx * 8;
            float4 o0, o1;
            o0.x = racc[r][0] + bb0.x;  o0.y = racc[r][1] + bb0.y;
            o0.z = racc[r][2] + bb0.z;  o0.w = racc[r][3] + bb0.w;
            o1.x = racc[r][4] + bb1.x;  o1.y = racc[r][5] + bb1.y;
            o1.z = racc[r][6] + bb1.z;  o1.w = racc[r][7] + bb1.w;
            *(float4*)(op)     = o0;
            *(float4*)(op + 4) = o1;
        }
    }
#undef ASF
#undef BSF
#endif
}

// ---------------------------------------------------------------------------
extern "C" void kernel_launch(void* const* d_in, const int* in_sizes, int n_in,
                              void* d_out, int out_size) {
    const float* x    = (const float*)d_in[0];
    const float* w    = (const float*)d_in[1];
    const float* bias = (const float*)d_in[2];
    float* out = (float*)d_out;

    const int Bdim = in_sizes[0] / K_DIM;   // 8192

    uint8_t* xpack = nullptr; uint8_t* wpack = nullptr;
    cudaGetSymbolAddress((void**)&xpack, g_xpack);
    cudaGetSymbolAddress((void**)&wpack, g_wpack);

    cudaFuncSetAttribute(vmm_main_kernel,
                         cudaFuncAttributeMaxDynamicSharedMemorySize, DYN_BYTES);

    pack_kernel<<<Bdim * 2, 256>>>(x, xpack, Bdim);
    pack_kernel<<<N_DIM * 2, 256>>>(w, wpack, N_DIM);

    dim3 grid(N_DIM / BN, Bdim / BM);       // (32, 64)
    vmm_main_kernel<<<grid, THREADS, DYN_BYTES>>>(x, w, bias, out);
}

// round 8
// speedup vs baseline: 11.3924x; 1.1036x over previous
#include <cuda_runtime.h>
#include <cuda_bf16.h>
#include <cstdint>

// ============================================================================
// HardwareVMMoperation: out = sum_{c<32} Q(x[:,128c:+128] @ W[:,128c:+128]^T) + bias
// B=8192, K=N=4096 fp32.  Q = clamp(+-2.56) -> *(255/2.56) -> rint -> back.
//
// tcgen05 bf16 3-term split GEMM, BM=256 (two m-subtiles share B smem tile),
// BN=128, KSUB=32, SW64-packed operand tiles, 4-stage bulk-copy pipeline,
// full-TMEM (512 col) chunk ping-pong, 16 epilogue warps.
//   - sm_103a pass (__CUDA_ARCH_FEAT_SM103_ALL): tcgen05 path
//   - plain sm_103 pass: FFMA2 SIMT fallback (compile-only insurance)
// ============================================================================

#if defined(__CUDA_ARCH__) && defined(__CUDA_ARCH_FEAT_SM103_ALL)
#define TC_ON 1
#else
#define TC_ON 0
#endif

#define K_DIM   4096
#define N_DIM   4096
#define BM      256                // per CTA (2 m-subtiles of 128)
#define BN      128
#define KSUB    32                 // K per pipeline stage
#define NSTAGE  4
#define TILE_B  8192               // 128 rows x 32 k x 2B, SW64-swizzled image
#define TPAIR   (2 * TILE_B)       // hi + lo
#define STAGE_BYTES (3 * TPAIR)    // A0 pair, A1 pair, B pair = 49152
#define NSS     (K_DIM / KSUB)     // 128 sub-stages
#define SUBS_PER_CHUNK 4           // 128 / 32
#define NCHUNK  32
#define THREADS 576                // 16 epi + 1 mma + 1 producer warps
#define MMA_WARP  16
#define PROD_WARP 17
#define IDESC   0x8200490u         // f32 acc, bf16 x bf16, M=128, N=128, K-major
#define DYN_BYTES (NSTAGE * STAGE_BYTES + 1024)

#define KB_TILES (K_DIM / KSUB)    // 128 k-tiles per row-tile
#define X_ROWTILES (8192 / 128)    // 64
#define W_ROWTILES (N_DIM / 128)   // 32

// packed hi/lo bf16 scratch (device globals = allowed scratch path)
__device__ __align__(128) uint8_t g_xpack[(size_t)X_ROWTILES * KB_TILES * TPAIR];
__device__ __align__(128) uint8_t g_wpack[(size_t)W_ROWTILES * KB_TILES * TPAIR];

// ---------------------------------------------------------------------------
__device__ __forceinline__ float quantize_partial(float p) {
    float y = fminf(fmaxf(p, -2.56f), 2.56f);
    y = y * (255.0f / 2.56f);   // 99.609375 exact
    y = rintf(y);               // round half to even
    return y * (2.56f / 255.0f);
}
__device__ __forceinline__ uint32_t smem_u32(const void* p) {
    return (uint32_t)__cvta_generic_to_shared(p);
}

#if TC_ON
// ---------------------------------------------------------------------------
__device__ __forceinline__ bool elect_one() {
    uint32_t p;
    asm volatile("{\n\t.reg .pred P;\n\telect.sync _|P, 0xFFFFFFFF;\n\t"
                 "selp.b32 %0, 1, 0, P;\n\t}" : "=r"(p));
    return p != 0;
}
__device__ __forceinline__ void mbar_init(uint32_t bar, uint32_t cnt) {
    asm volatile("mbarrier.init.shared.b64 [%0], %1;" :: "r"(bar), "r"(cnt) : "memory");
}
__device__ __forceinline__ void mbar_expect_tx(uint32_t bar, uint32_t bytes) {
    asm volatile("mbarrier.arrive.expect_tx.shared.b64 _, [%0], %1;"
                 :: "r"(bar), "r"(bytes) : "memory");
}
__device__ __forceinline__ void mbar_arrive(uint32_t bar) {
    asm volatile("mbarrier.arrive.shared.b64 _, [%0];" :: "r"(bar) : "memory");
}
__device__ __forceinline__ void mbar_wait(uint32_t bar, uint32_t parity) {
    asm volatile("{\n\t.reg .pred P;\n"
        "WL%=:\n\t"
        "mbarrier.try_wait.parity.acquire.cta.shared::cta.b64 P, [%0], %1, 0x989680;\n\t"
        "@P bra WD%=;\n\t"
        "bra WL%=;\n"
        "WD%=:\n\t}"
        :: "r"(bar), "r"(parity) : "memory");
}
__device__ __forceinline__ void bulk_cp(uint32_t dst, const void* src, uint32_t bytes,
                                        uint32_t bar) {
    asm volatile("cp.async.bulk.shared::cluster.global.mbarrier::complete_tx::bytes "
                 "[%0], [%1], %2, [%3];"
                 :: "r"(dst), "l"(src), "r"(bytes), "r"(bar) : "memory");
}
// SW64 K-major descriptor: layout=4, version=1, SBO=32 (512B = 8 rows x 64B), LBO=1
__device__ __forceinline__ uint64_t make_desc64(uint32_t addr) {
    const uint64_t base = (4ULL << 61) | (1ULL << 46) | (32ULL << 32) | (1ULL << 16);
    return base | (uint64_t)((addr >> 4) & 0x3FFF);
}
__device__ __forceinline__ void mma_ss(uint32_t d, uint64_t a, uint64_t b, uint32_t en) {
    asm volatile("{\n\t.reg .pred p;\n\tsetp.ne.u32 p, %4, 0;\n\t"
        "tcgen05.mma.cta_group::1.kind::f16 [%0], %1, %2, %3, {%5, %5, %5, %5}, p;\n\t}"
        :: "r"(d), "l"(a), "l"(b), "r"(IDESC), "r"(en), "r"(0u) : "memory");
}
__device__ __forceinline__ void tc_commit(uint32_t bar) {
    asm volatile("tcgen05.commit.cta_group::1.mbarrier::arrive::one.shared::cluster.b64 [%0];"
                 :: "r"(bar) : "memory");
}
__device__ __forceinline__ void ldtm16(uint32_t* r, uint32_t addr) {
    asm volatile("tcgen05.ld.sync.aligned.32x32b.x16.b32 "
        "{%0,%1,%2,%3,%4,%5,%6,%7,%8,%9,%10,%11,%12,%13,%14,%15}, [%16];"
        : "=r"(r[0]), "=r"(r[1]), "=r"(r[2]), "=r"(r[3]),
          "=r"(r[4]), "=r"(r[5]), "=r"(r[6]), "=r"(r[7]),
          "=r"(r[8]), "=r"(r[9]), "=r"(r[10]), "=r"(r[11]),
          "=r"(r[12]), "=r"(r[13]), "=r"(r[14]), "=r"(r[15])
        : "r"(addr));
}
__device__ __forceinline__ void tc_wait_ld()      { asm volatile("tcgen05.wait::ld.sync.aligned;" ::: "memory"); }
__device__ __forceinline__ void tc_fence_before() { asm volatile("tcgen05.fence::before_thread_sync;" ::: "memory"); }
__device__ __forceinline__ void tc_fence_after()  { asm volatile("tcgen05.fence::after_thread_sync;" ::: "memory"); }
#else
__device__ __forceinline__ unsigned long long dup2(float v) {
    unsigned long long r;
    asm("mov.b64 %0, {%1, %1};" : "=l"(r) : "f"(v));
    return r;
}
__device__ __forceinline__ void ffma2(unsigned long long &d,
                                      unsigned long long a, unsigned long long b) {
    asm("fma.rn.f32x2 %0, %1, %2, %0;" : "+l"(d) : "l"(a), "l"(b));
}
__device__ __forceinline__ float2 unpack2(unsigned long long v) {
    float2 f;
    asm("mov.b64 {%0, %1}, %2;" : "=f"(f.x), "=f"(f.y) : "l"(v));
    return f;
}
#endif

// ---------------------------------------------------------------------------
// Pre-pass: fp32 [rows,4096] -> hi/lo bf16, SW64-swizzled 128x32 tiles.
// dst: [rowtile][ktile][hi 8192B | lo 8192B], tile byte = swz64(r*64 + c*2)
// ---------------------------------------------------------------------------
__global__ void __launch_bounds__(256)
pack_kernel(const float* __restrict__ src, uint8_t* __restrict__ dst, int rows) {
#if TC_ON
    int idx = blockIdx.x * blockDim.x + threadIdx.x;   // one thread = 8 k's (16B out)
    int kq  = idx & (K_DIM / 8 - 1);                   // 0..511
    int row = idx >> 9;
    if (row >= rows) return;

    const float4* s = (const float4*)(src + (size_t)row * K_DIM + kq * 8);
    float4 v0 = s[0], v1 = s[1];
    float f[8] = {v0.x, v0.y, v0.z, v0.w, v1.x, v1.y, v1.z, v1.w};

    uint32_t hi[4], lo[4];
#pragma unroll
    for (int i = 0; i < 4; ++i) {
        __nv_bfloat16 h0 = __float2bfloat16_rn(f[2 * i]);
        __nv_bfloat16 h1 = __float2bfloat16_rn(f[2 * i + 1]);
        __nv_bfloat16 l0 = __float2bfloat16_rn(f[2 * i]     - __bfloat162float(h0));
        __nv_bfloat16 l1 = __float2bfloat16_rn(f[2 * i + 1] - __bfloat162float(h1));
        hi[i] = (uint32_t)__bfloat16_as_ushort(h0) | ((uint32_t)__bfloat16_as_ushort(h1) << 16);
        lo[i] = (uint32_t)__bfloat16_as_ushort(l0) | ((uint32_t)__bfloat16_as_ushort(l1) << 16);
    }

    int rb = row >> 7, r = row & 127;
    int k  = kq * 8;
    int kb = k >> 5;                 // 32-k tile
    int c  = k & 31;
    uint32_t off = (uint32_t)(r * 64 + c * 2);
    off ^= (off >> 3) & 0x30;        // SW64 swizzle (16B chunks preserved)
    size_t tbase = ((size_t)rb * KB_TILES + kb) * TPAIR;
    *(uint4*)(dst + tbase + off)          = make_uint4(hi[0], hi[1], hi[2], hi[3]);
    *(uint4*)(dst + tbase + TILE_B + off) = make_uint4(lo[0], lo[1], lo[2], lo[3]);
#else
    (void)src; (void)dst; (void)rows;
#endif
}

// ---------------------------------------------------------------------------
// Main kernel: grid (N/128, B/256), 576 threads, DYN_BYTES dynamic smem
// ---------------------------------------------------------------------------
__global__ void __launch_bounds__(THREADS, 1)
vmm_main_kernel(const float* __restrict__ x, const float* __restrict__ w,
                const float* __restrict__ bias, float* __restrict__ out) {
    extern __shared__ uint8_t dyn[];
#if TC_ON
    // ======================= tcgen05 path =======================
    __shared__ __align__(8) uint64_t s_full[NSTAGE], s_empty[NSTAGE];
    __shared__ __align__(8) uint64_t s_mma_done[2], s_epi_done[2];
    __shared__ uint32_t s_tmem_ptr;

    const uint32_t sbase = (smem_u32(dyn) + 1023) & ~1023u;
    const int tid  = threadIdx.x;
    const int wid  = tid >> 5;
    const int lane = tid & 31;
    const int nblk = blockIdx.x, mblk = blockIdx.y;
    const int n0 = nblk * BN, m0 = mblk * BM;

    if (tid == 0) {
#pragma unroll
        for (int s = 0; s < NSTAGE; ++s) {
            mbar_init(smem_u32(&s_full[s]), 1);
            mbar_init(smem_u32(&s_empty[s]), 1);
        }
        mbar_init(smem_u32(&s_mma_done[0]), 1);
        mbar_init(smem_u32(&s_mma_done[1]), 1);
        mbar_init(smem_u32(&s_epi_done[0]), 512);
        mbar_init(smem_u32(&s_epi_done[1]), 512);
    }
    if (wid == MMA_WARP) {
        asm volatile("tcgen05.alloc.cta_group::1.sync.aligned.shared::cta.b32 [%0], %1;"
                     :: "r"(smem_u32(&s_tmem_ptr)), "r"(512u) : "memory");
    }
    __syncthreads();
    const uint32_t tmem = s_tmem_ptr;

    if (wid == PROD_WARP) {
        // ---- producer: A0, A1, B tile pairs per sub-stage ----
        if (elect_one()) {
            const uint8_t* a0src = g_xpack + ((size_t)(mblk * 2 + 0) * KB_TILES) * TPAIR;
            const uint8_t* a1src = g_xpack + ((size_t)(mblk * 2 + 1) * KB_TILES) * TPAIR;
            const uint8_t* bsrc  = g_wpack + ((size_t)nblk * KB_TILES) * TPAIR;
            int eph[NSTAGE] = {1, 1, 1, 1};
            for (int s = 0; s < NSS; ++s) {
                int st = s & (NSTAGE - 1);
                mbar_wait(smem_u32(&s_empty[st]), eph[st]); eph[st] ^= 1;
                uint32_t d = sbase + st * STAGE_BYTES;
                uint32_t fb = smem_u32(&s_full[st]);
                mbar_expect_tx(fb, STAGE_BYTES);
                bulk_cp(d,             a0src + (size_t)s * TPAIR, TPAIR, fb);
                bulk_cp(d + TPAIR,     a1src + (size_t)s * TPAIR, TPAIR, fb);
                bulk_cp(d + 2 * TPAIR, bsrc  + (size_t)s * TPAIR, TPAIR, fb);
            }
        }
    } else if (wid == MMA_WARP) {
        // ---- MMA: per chunk, 4 subs x 2 m-subtiles x 3 terms x 2 k-steps ----
        if (elect_one()) {
            int fph[NSTAGE] = {0, 0, 0, 0};
            int eph[2] = {1, 1};
            int st = 0;
            for (int c = 0; c < NCHUNK; ++c) {
                int slot = c & 1;
                mbar_wait(smem_u32(&s_epi_done[slot]), eph[slot]); eph[slot] ^= 1;
                tc_fence_after();
                uint32_t d0 = tmem + (slot * 2 + 0) * 128;
                uint32_t d1 = tmem + (slot * 2 + 1) * 128;
                for (int sub = 0; sub < SUBS_PER_CHUNK; ++sub) {
                    mbar_wait(smem_u32(&s_full[st]), fph[st]); fph[st] ^= 1;
                    uint32_t a = sbase + st * STAGE_BYTES;
                    uint64_t A0h = make_desc64(a);
                    uint64_t A0l = make_desc64(a + TILE_B);
                    uint64_t A1h = make_desc64(a + TPAIR);
                    uint64_t A1l = make_desc64(a + TPAIR + TILE_B);
                    uint64_t Bh  = make_desc64(a + 2 * TPAIR);
                    uint64_t Bl  = make_desc64(a + 2 * TPAIR + TILE_B);
                    uint64_t t0a[3] = {A0h, A0l, A0h};
                    uint64_t t1a[3] = {A1h, A1l, A1h};
                    uint64_t tb[3]  = {Bh,  Bh,  Bl};
#pragma unroll
                    for (int t = 0; t < 3; ++t)
#pragma unroll
                        for (int ks = 0; ks < 2; ++ks) {
                            uint32_t en = !(sub == 0 && t == 0 && ks == 0);
                            mma_ss(d0, t0a[t] + ks * 2, tb[t] + ks * 2, en);
                            mma_ss(d1, t1a[t] + ks * 2, tb[t] + ks * 2, en);
                        }
                    tc_commit(smem_u32(&s_empty[st]));   // stage free when drained
                    st = (st + 1) & (NSTAGE - 1);
                }
                tc_commit(smem_u32(&s_mma_done[slot])); // chunk D (both m) ready
            }
        }
    } else {
        // ---- epilogue: 16 warps; wid = m*8 + grp*4 + sp ----
        const int msub = wid >> 3;          // m-subtile 0/1
        const int grp  = (wid >> 2) & 1;    // column half
        const int sp   = wid & 3;           // TMEM subpartition (rows sp*32..+31)
        float racc[64];
#pragma unroll
        for (int i = 0; i < 64; ++i) racc[i] = 0.0f;

        int mph[2] = {0, 0};
        for (int c = 0; c < NCHUNK; ++c) {
            int slot = c & 1;
            mbar_wait(smem_u32(&s_mma_done[slot]), mph[slot]); mph[slot] ^= 1;
            tc_fence_after();
            uint32_t base = tmem + (slot * 2 + msub) * 128 + grp * 64;
#pragma unroll
            for (int b = 0; b < 4; ++b) {
                uint32_t dr[16];
                ldtm16(dr, base + b * 16);
                tc_wait_ld();
#pragma unroll
                for (int j = 0; j < 16; ++j)
                    racc[b * 16 + j] += quantize_partial(__uint_as_float(dr[j]));
            }
            tc_fence_before();
            mbar_arrive(smem_u32(&s_epi_done[slot]));
        }

        const int m  = m0 + msub * 128 + sp * 32 + lane;
        const float* bp = bias + n0 + grp * 64;
        float* op = out + (size_t)m * N_DIM + n0 + grp * 64;
#pragma unroll
        for (int q = 0; q < 16; ++q) {
            float4 bb = *(const float4*)(bp + q * 4);
            float4 o;
            o.x = racc[q * 4 + 0] + bb.x;
            o.y = racc[q * 4 + 1] + bb.y;
            o.z = racc[q * 4 + 2] + bb.z;
            o.w = racc[q * 4 + 3] + bb.w;
            *(float4*)(op + q * 4) = o;
        }
    }

    __syncthreads();
    if (wid == MMA_WARP) {
        asm volatile("tcgen05.relinquish_alloc_permit.cta_group::1.sync.aligned;");
        asm volatile("tcgen05.dealloc.cta_group::1.sync.aligned.b32 %0, %1;"
                     :: "r"(tmem), "r"(512u));
    }
#else
    // ======================= FFMA2 fallback (plain sm_103; never runs) =======
    float* As = (float*)dyn;
    float* Bs = As + 2 * 16 * 128;
#define ASF(b, k, r) As[((b) * 16 + (k)) * 128 + (r)]
#define BSF(b, k, r) Bs[((b) * 16 + (k)) * 128 + (r)]

    const int tid = threadIdx.x;
    const bool act = tid < 256;
    const int tx  = tid & 15;
    const int ty  = (tid >> 4) & 15;
    const int n0  = blockIdx.x * BN;
    const int ldr = (tid >> 2) & 63;
    const int ldq = tid & 3;

    for (int msub = 0; msub < 2; ++msub) {
        const int m0 = (blockIdx.y * 2 + msub) * 128;
        const float* ax = x + (size_t)(m0 + ldr) * K_DIM + ldq * 4;
        const float* bx = w + (size_t)(n0 + ldr) * K_DIM + ldq * 4;

        unsigned long long pacc[4][8];
        float racc[8][8];
#pragma unroll
        for (int i = 0; i < 4; ++i)
#pragma unroll
            for (int j = 0; j < 8; ++j) pacc[i][j] = 0ULL;
#pragma unroll
        for (int i = 0; i < 8; ++i)
#pragma unroll
            for (int j = 0; j < 8; ++j) racc[i][j] = 0.0f;

        __syncthreads();
        if (act) {
            float4 a0 = *(const float4*)(ax);
            float4 a1 = *(const float4*)(ax + (size_t)64 * K_DIM);
            float4 b0 = *(const float4*)(bx);
            float4 b1 = *(const float4*)(bx + (size_t)64 * K_DIM);
            ASF(0, ldq * 4 + 0, ldr) = a0.x;  ASF(0, ldq * 4 + 1, ldr) = a0.y;
            ASF(0, ldq * 4 + 2, ldr) = a0.z;  ASF(0, ldq * 4 + 3, ldr) = a0.w;
            ASF(0, ldq * 4 + 0, ldr + 64) = a1.x;  ASF(0, ldq * 4 + 1, ldr + 64) = a1.y;
            ASF(0, ldq * 4 + 2, ldr + 64) = a1.z;  ASF(0, ldq * 4 + 3, ldr + 64) = a1.w;
            BSF(0, ldq * 4 + 0, ldr) = b0.x;  BSF(0, ldq * 4 + 1, ldr) = b0.y;
            BSF(0, ldq * 4 + 2, ldr) = b0.z;  BSF(0, ldq * 4 + 3, ldr) = b0.w;
            BSF(0, ldq * 4 + 0, ldr + 64) = b1.x;  BSF(0, ldq * 4 + 1, ldr + 64) = b1.y;
            BSF(0, ldq * 4 + 2, ldr + 64) = b1.z;  BSF(0, ldq * 4 + 3, ldr + 64) = b1.w;
        }
        __syncthreads();

        int buf = 0;
        const int NSUB_F = K_DIM / 16;
        for (int s = 0; s < NSUB_F; ++s) {
            float4 a0, a1, b0, b1;
            const bool has_next = (s + 1 < NSUB_F);
            if (act && has_next) {
                const float* ap = ax + (size_t)(s + 1) * 16;
                const float* bp = bx + (size_t)(s + 1) * 16;
                a0 = *(const float4*)(ap);
                a1 = *(const float4*)(ap + (size_t)64 * K_DIM);
                b0 = *(const float4*)(bp);
                b1 = *(const float4*)(bp + (size_t)64 * K_DIM);
            }
            if (act) {
#pragma unroll
                for (int kk = 0; kk < 16; ++kk) {
                    ulonglong2 av0 = *(const ulonglong2*)&ASF(buf, kk, ty * 8);
                    ulonglong2 av1 = *(const ulonglong2*)&ASF(buf, kk, ty * 8 + 4);
                    float4 bv0 = *(const float4*)&BSF(buf, kk, tx * 8);
                    float4 bv1 = *(const float4*)&BSF(buf, kk, tx * 8 + 4);
                    unsigned long long am[4] = {av0.x, av0.y, av1.x, av1.y};
                    unsigned long long bd[8] = {dup2(bv0.x), dup2(bv0.y), dup2(bv0.z), dup2(bv0.w),
                                                dup2(bv1.x), dup2(bv1.y), dup2(bv1.z), dup2(bv1.w)};
#pragma unroll
                    for (int mi = 0; mi < 4; ++mi)
#pragma unroll
                        for (int j = 0; j < 8; ++j)
                            ffma2(pacc[mi][j], am[mi], bd[j]);
                }
                if ((s & 7) == 7) {
#pragma unroll
                    for (int mi = 0; mi < 4; ++mi)
#pragma unroll
                        for (int j = 0; j < 8; ++j) {
                            float2 p = unpack2(pacc[mi][j]);
                            racc[2 * mi + 0][j] += quantize_partial(p.x);
                            racc[2 * mi + 1][j] += quantize_partial(p.y);
                            pacc[mi][j] = 0ULL;
                        }
                }
            }
            if (has_next) {
                const int nb = buf ^ 1;
                if (act) {
                    ASF(nb, ldq * 4 + 0, ldr) = a0.x;  ASF(nb, ldq * 4 + 1, ldr) = a0.y;
                    ASF(nb, ldq * 4 + 2, ldr) = a0.z;  ASF(nb, ldq * 4 + 3, ldr) = a0.w;
                    ASF(nb, ldq * 4 + 0, ldr + 64) = a1.x;  ASF(nb, ldq * 4 + 1, ldr + 64) = a1.y;
                    ASF(nb, ldq * 4 + 2, ldr + 64) = a1.z;  ASF(nb, ldq * 4 + 3, ldr + 64) = a1.w;
                    BSF(nb, ldq * 4 + 0, ldr) = b0.x;  BSF(nb, ldq * 4 + 1, ldr) = b0.y;
                    BSF(nb, ldq * 4 + 2, ldr) = b0.z;  BSF(nb, ldq * 4 + 3, ldr) = b0.w;
                    BSF(nb, ldq * 4 + 0, ldr + 64) = b1.x;  BSF(nb, ldq * 4 + 1, ldr + 64) = b1.y;
                    BSF(nb, ldq * 4 + 2, ldr + 64) = b1.z;  BSF(nb, ldq * 4 + 3, ldr + 64) = b1.w;
                }
                __syncthreads();
                buf = nb;
            }
        }

        if (act) {
            const float* bptr = bias + n0 + tx * 8;
            float4 bb0 = *(const float4*)(bptr);
            float4 bb1 = *(const float4*)(bptr + 4);
#pragma unroll
            for (int r = 0; r < 8; ++r) {
                float* op = out + (size_t)(m0 + ty * 8 + r) * N_DIM + n0 + tx * 8;
                float4 o0, o1;
                o0.x = racc[r][0] + bb0.x;  o0.y = racc[r][1] + bb0.y;
                o0.z = racc[r][2] + bb0.z;  o0.w = racc[r][3] + bb0.w;
                o1.x = racc[r][4] + bb1.x;  o1.y = racc[r][5] + bb1.y;
                o1.z = racc[r][6] + bb1.z;  o1.w = racc[r][7] + bb1.w;
                *(float4*)(op)     = o0;
                *(float4*)(op + 4) = o1;
            }
        }
    }
#undef ASF
#undef BSF
#endif
}

// ---------------------------------------------------------------------------
extern "C" void kernel_launch(void* const* d_in, const int* in_sizes, int n_in,
                              void* d_out, int out_size) {
    const float* x    = (const float*)d_in[0];
    const float* w    = (const float*)d_in[1];
    const float* bias = (const float*)d_in[2];
    float* out = (float*)d_out;

    const int Bdim = in_sizes[0] / K_DIM;   // 8192

    uint8_t* xpack = nullptr; uint8_t* wpack = nullptr;
    cudaGetSymbolAddress((void**)&xpack, g_xpack);
    cudaGetSymbolAddress((void**)&wpack, g_wpack);

    cudaFuncSetAttribute(vmm_main_kernel,
                         cudaFuncAttributeMaxDynamicSharedMemorySize, DYN_BYTES);

    pack_kernel<<<Bdim * 2, 256>>>(x, xpack, Bdim);
    pack_kernel<<<N_DIM * 2, 256>>>(w, wpack, N_DIM);

    dim3 grid(N_DIM / BN, Bdim / BM);       // (32, 32)
    vmm_main_kernel<<<grid, THREADS, DYN_BYTES>>>(bias ? x : x, w, bias, out);
}

// round 9
// speedup vs baseline: 11.5444x; 1.0133x over previous
#include <cuda_runtime.h>
#include <cuda_bf16.h>
#include <cstdint>

// ============================================================================
// HardwareVMMoperation: out = sum_{c<32} Q(x[:,128c:+128] @ W[:,128c:+128]^T) + bias
// B=8192, K=N=4096 fp32.  Q = clamp(+-2.56) -> *(255/2.56) -> rint -> back.
//
// tcgen05 bf16 3-term split GEMM, BM=256, BN=128, KSUB=32, SW64 tiles,
// 4-stage bulk-copy pipeline, TMEM ping-pong, 16 epilogue warps.
// NEW (R8): cluster-2 along n; A (x) tiles delivered by multicast bulk copy
// (one L2 read serves both CTAs); stage-empty barriers count=2 signalled by
// commit-multicast from both CTAs' MMA warps.
//   - sm_103a pass: tcgen05 path;  plain sm_103 pass: FFMA2 fallback.
// ============================================================================

#if defined(__CUDA_ARCH__) && defined(__CUDA_ARCH_FEAT_SM103_ALL)
#define TC_ON 1
#else
#define TC_ON 0
#endif

#define K_DIM   4096
#define N_DIM   4096
#define BM      256                // per CTA (2 m-subtiles of 128)
#define BN      128
#define KSUB    32
#define NSTAGE  4
#define TILE_B  8192               // 128 rows x 32 k x 2B, SW64-swizzled
#define TPAIR   (2 * TILE_B)
#define STAGE_BYTES (3 * TPAIR)    // A0 pair, A1 pair, B pair = 49152
#define NSS     (K_DIM / KSUB)     // 128
#define SUBS_PER_CHUNK 4
#define NCHUNK  32
#define THREADS 576
#define MMA_WARP  16
#define PROD_WARP 17
#define IDESC   0x8200490u
#define DYN_BYTES (NSTAGE * STAGE_BYTES + 1024)
#define CL_MASK 0x3                // both cluster CTAs

#define KB_TILES (K_DIM / KSUB)    // 128
#define X_ROWTILES (8192 / 128)    // 64
#define W_ROWTILES (N_DIM / 128)   // 32

__device__ __align__(128) uint8_t g_xpack[(size_t)X_ROWTILES * KB_TILES * TPAIR];
__device__ __align__(128) uint8_t g_wpack[(size_t)W_ROWTILES * KB_TILES * TPAIR];

// ---------------------------------------------------------------------------
__device__ __forceinline__ float quantize_partial(float p) {
    float y = fminf(fmaxf(p, -2.56f), 2.56f);
    y = y * (255.0f / 2.56f);   // 99.609375 exact
    y = rintf(y);               // round half to even
    return y * (2.56f / 255.0f);
}
__device__ __forceinline__ uint32_t smem_u32(const void* p) {
    return (uint32_t)__cvta_generic_to_shared(p);
}

#if TC_ON
// ---------------------------------------------------------------------------
__device__ __forceinline__ bool elect_one() {
    uint32_t p;
    asm volatile("{\n\t.reg .pred P;\n\telect.sync _|P, 0xFFFFFFFF;\n\t"
                 "selp.b32 %0, 1, 0, P;\n\t}" : "=r"(p));
    return p != 0;
}
__device__ __forceinline__ uint32_t ctarank() {
    uint32_t r;
    asm("mov.u32 %0, %%cluster_ctarank;" : "=r"(r));
    return r;
}
__device__ __forceinline__ void cluster_sync_all() {
    asm volatile("barrier.cluster.arrive.aligned;" ::: "memory");
    asm volatile("barrier.cluster.wait.aligned;" ::: "memory");
}
__device__ __forceinline__ void mbar_init(uint32_t bar, uint32_t cnt) {
    asm volatile("mbarrier.init.shared.b64 [%0], %1;" :: "r"(bar), "r"(cnt) : "memory");
}
__device__ __forceinline__ void mbar_expect_tx(uint32_t bar, uint32_t bytes) {
    asm volatile("mbarrier.arrive.expect_tx.shared.b64 _, [%0], %1;"
                 :: "r"(bar), "r"(bytes) : "memory");
}
__device__ __forceinline__ void mbar_arrive(uint32_t bar) {
    asm volatile("mbarrier.arrive.shared.b64 _, [%0];" :: "r"(bar) : "memory");
}
__device__ __forceinline__ void mbar_wait(uint32_t bar, uint32_t parity) {
    asm volatile("{\n\t.reg .pred P;\n"
        "WL%=:\n\t"
        "mbarrier.try_wait.parity.acquire.cta.shared::cta.b64 P, [%0], %1, 0x989680;\n\t"
        "@P bra WD%=;\n\t"
        "bra WL%=;\n"
        "WD%=:\n\t}"
        :: "r"(bar), "r"(parity) : "memory");
}
__device__ __forceinline__ void bulk_cp(uint32_t dst, const void* src, uint32_t bytes,
                                        uint32_t bar) {
    asm volatile("cp.async.bulk.shared::cluster.global.mbarrier::complete_tx::bytes "
                 "[%0], [%1], %2, [%3];"
                 :: "r"(dst), "l"(src), "r"(bytes), "r"(bar) : "memory");
}
__device__ __forceinline__ void bulk_cp_mcast(uint32_t dst, const void* src, uint32_t bytes,
                                              uint32_t bar, uint16_t mask) {
    asm volatile("cp.async.bulk.shared::cluster.global.mbarrier::complete_tx::bytes"
                 ".multicast::cluster [%0], [%1], %2, [%3], %4;"
                 :: "r"(dst), "l"(src), "r"(bytes), "r"(bar), "h"(mask) : "memory");
}
// SW64 K-major descriptor: layout=4, version=1, SBO=32, LBO=1
__device__ __forceinline__ uint64_t make_desc64(uint32_t addr) {
    const uint64_t base = (4ULL << 61) | (1ULL << 46) | (32ULL << 32) | (1ULL << 16);
    return base | (uint64_t)((addr >> 4) & 0x3FFF);
}
__device__ __forceinline__ void mma_ss(uint32_t d, uint64_t a, uint64_t b, uint32_t en) {
    asm volatile("{\n\t.reg .pred p;\n\tsetp.ne.u32 p, %4, 0;\n\t"
        "tcgen05.mma.cta_group::1.kind::f16 [%0], %1, %2, %3, {%5, %5, %5, %5}, p;\n\t}"
        :: "r"(d), "l"(a), "l"(b), "r"(IDESC), "r"(en), "r"(0u) : "memory");
}
__device__ __forceinline__ void tc_commit(uint32_t bar) {
    asm volatile("tcgen05.commit.cta_group::1.mbarrier::arrive::one.shared::cluster.b64 [%0];"
                 :: "r"(bar) : "memory");
}
__device__ __forceinline__ void tc_commit_mcast(uint32_t bar, uint16_t mask) {
    asm volatile("tcgen05.commit.cta_group::1.mbarrier::arrive::one.shared::cluster"
                 ".multicast::cluster.b64 [%0], %1;"
                 :: "r"(bar), "h"(mask) : "memory");
}
__device__ __forceinline__ void ldtm16(uint32_t* r, uint32_t addr) {
    asm volatile("tcgen05.ld.sync.aligned.32x32b.x16.b32 "
        "{%0,%1,%2,%3,%4,%5,%6,%7,%8,%9,%10,%11,%12,%13,%14,%15}, [%16];"
        : "=r"(r[0]), "=r"(r[1]), "=r"(r[2]), "=r"(r[3]),
          "=r"(r[4]), "=r"(r[5]), "=r"(r[6]), "=r"(r[7]),
          "=r"(r[8]), "=r"(r[9]), "=r"(r[10]), "=r"(r[11]),
          "=r"(r[12]), "=r"(r[13]), "=r"(r[14]), "=r"(r[15])
        : "r"(addr));
}
__device__ __forceinline__ void tc_wait_ld()      { asm volatile("tcgen05.wait::ld.sync.aligned;" ::: "memory"); }
__device__ __forceinline__ void tc_fence_before() { asm volatile("tcgen05.fence::before_thread_sync;" ::: "memory"); }
__device__ __forceinline__ void tc_fence_after()  { asm volatile("tcgen05.fence::after_thread_sync;" ::: "memory"); }
#else
__device__ __forceinline__ unsigned long long dup2(float v) {
    unsigned long long r;
    asm("mov.b64 %0, {%1, %1};" : "=l"(r) : "f"(v));
    return r;
}
__device__ __forceinline__ void ffma2(unsigned long long &d,
                                      unsigned long long a, unsigned long long b) {
    asm("fma.rn.f32x2 %0, %1, %2, %0;" : "+l"(d) : "l"(a), "l"(b));
}
__device__ __forceinline__ float2 unpack2(unsigned long long v) {
    float2 f;
    asm("mov.b64 {%0, %1}, %2;" : "=f"(f.x), "=f"(f.y) : "l"(v));
    return f;
}
#endif

// ---------------------------------------------------------------------------
// Pre-pass: fp32 [rows,4096] -> hi/lo bf16, SW64-swizzled 128x32 tiles.
// ---------------------------------------------------------------------------
__global__ void __launch_bounds__(256)
pack_kernel(const float* __restrict__ src, uint8_t* __restrict__ dst, int rows) {
#if TC_ON
    int idx = blockIdx.x * blockDim.x + threadIdx.x;   // one thread = 8 k's
    int kq  = idx & (K_DIM / 8 - 1);
    int row = idx >> 9;
    if (row >= rows) return;

    const float4* s = (const float4*)(src + (size_t)row * K_DIM + kq * 8);
    float4 v0 = s[0], v1 = s[1];
    float f[8] = {v0.x, v0.y, v0.z, v0.w, v1.x, v1.y, v1.z, v1.w};

    uint32_t hi[4], lo[4];
#pragma unroll
    for (int i = 0; i < 4; ++i) {
        __nv_bfloat16 h0 = __float2bfloat16_rn(f[2 * i]);
        __nv_bfloat16 h1 = __float2bfloat16_rn(f[2 * i + 1]);
        __nv_bfloat16 l0 = __float2bfloat16_rn(f[2 * i]     - __bfloat162float(h0));
        __nv_bfloat16 l1 = __float2bfloat16_rn(f[2 * i + 1] - __bfloat162float(h1));
        hi[i] = (uint32_t)__bfloat16_as_ushort(h0) | ((uint32_t)__bfloat16_as_ushort(h1) << 16);
        lo[i] = (uint32_t)__bfloat16_as_ushort(l0) | ((uint32_t)__bfloat16_as_ushort(l1) << 16);
    }

    int rb = row >> 7, r = row & 127;
    int k  = kq * 8;
    int kb = k >> 5;
    int c  = k & 31;
    uint32_t off = (uint32_t)(r * 64 + c * 2);
    off ^= (off >> 3) & 0x30;        // SW64 swizzle
    size_t tbase = ((size_t)rb * KB_TILES + kb) * TPAIR;
    *(uint4*)(dst + tbase + off)          = make_uint4(hi[0], hi[1], hi[2], hi[3]);
    *(uint4*)(dst + tbase + TILE_B + off) = make_uint4(lo[0], lo[1], lo[2], lo[3]);
#else
    (void)src; (void)dst; (void)rows;
#endif
}

// ---------------------------------------------------------------------------
// Main kernel: grid (N/128, B/256), cluster (2,1,1), 576 threads
// ---------------------------------------------------------------------------
__global__ void __launch_bounds__(THREADS, 1) __cluster_dims__(2, 1, 1)
vmm_main_kernel(const float* __restrict__ x, const float* __restrict__ w,
                const float* __restrict__ bias, float* __restrict__ out) {
    extern __shared__ uint8_t dyn[];
#if TC_ON
    // ======================= tcgen05 path =======================
    __shared__ __align__(8) uint64_t s_full[NSTAGE], s_empty[NSTAGE];
    __shared__ __align__(8) uint64_t s_mma_done[2], s_epi_done[2];
    __shared__ uint32_t s_tmem_ptr;

    const uint32_t sbase = (smem_u32(dyn) + 1023) & ~1023u;
    const int tid  = threadIdx.x;
    const int wid  = tid >> 5;
    const int lane = tid & 31;
    const int nblk = blockIdx.x, mblk = blockIdx.y;
    const int n0 = nblk * BN, m0 = mblk * BM;
    const uint32_t rank = ctarank();   // 0/1 within n-pair

    if (tid == 0) {
#pragma unroll
        for (int s = 0; s < NSTAGE; ++s) {
            mbar_init(smem_u32(&s_full[s]), 1);
            mbar_init(smem_u32(&s_empty[s]), 2);   // both CTAs' MMA warps arrive
        }
        mbar_init(smem_u32(&s_mma_done[0]), 1);
        mbar_init(smem_u32(&s_mma_done[1]), 1);
        mbar_init(smem_u32(&s_epi_done[0]), 512);
        mbar_init(smem_u32(&s_epi_done[1]), 512);
    }
    if (wid == MMA_WARP) {
        asm volatile("tcgen05.alloc.cta_group::1.sync.aligned.shared::cta.b32 [%0], %1;"
                     :: "r"(smem_u32(&s_tmem_ptr)), "r"(512u) : "memory");
    }
    __syncthreads();
    cluster_sync_all();               // peer barriers visible before any multicast
    const uint32_t tmem = s_tmem_ptr;

    if (wid == PROD_WARP) {
        // ---- producer: rank0 multicasts A pair to both CTAs; each loads its B ----
        if (elect_one()) {
            const uint8_t* a0src = g_xpack + ((size_t)(mblk * 2 + 0) * KB_TILES) * TPAIR;
            const uint8_t* a1src = g_xpack + ((size_t)(mblk * 2 + 1) * KB_TILES) * TPAIR;
            const uint8_t* bsrc  = g_wpack + ((size_t)nblk * KB_TILES) * TPAIR;
            int eph[NSTAGE] = {1, 1, 1, 1};
            for (int s = 0; s < NSS; ++s) {
                int st = s & (NSTAGE - 1);
                mbar_wait(smem_u32(&s_empty[st]), eph[st]); eph[st] ^= 1;
                uint32_t d = sbase + st * STAGE_BYTES;
                uint32_t fb = smem_u32(&s_full[st]);
                mbar_expect_tx(fb, STAGE_BYTES);
                if (rank == 0) {
                    bulk_cp_mcast(d,         a0src + (size_t)s * TPAIR, TPAIR, fb, CL_MASK);
                    bulk_cp_mcast(d + TPAIR, a1src + (size_t)s * TPAIR, TPAIR, fb, CL_MASK);
                }
                bulk_cp(d + 2 * TPAIR, bsrc + (size_t)s * TPAIR, TPAIR, fb);
            }
        }
    } else if (wid == MMA_WARP) {
        // ---- MMA: per chunk, 4 subs x 2 m-subtiles x 3 terms x 2 k-steps ----
        if (elect_one()) {
            int fph[NSTAGE] = {0, 0, 0, 0};
            int eph[2] = {1, 1};
            int st = 0;
            for (int c = 0; c < NCHUNK; ++c) {
                int slot = c & 1;
                mbar_wait(smem_u32(&s_epi_done[slot]), eph[slot]); eph[slot] ^= 1;
                tc_fence_after();
                uint32_t d0 = tmem + (slot * 2 + 0) * 128;
                uint32_t d1 = tmem + (slot * 2 + 1) * 128;
                for (int sub = 0; sub < SUBS_PER_CHUNK; ++sub) {
                    mbar_wait(smem_u32(&s_full[st]), fph[st]); fph[st] ^= 1;
                    uint32_t a = sbase + st * STAGE_BYTES;
                    uint64_t A0h = make_desc64(a);
                    uint64_t A0l = make_desc64(a + TILE_B);
                    uint64_t A1h = make_desc64(a + TPAIR);
                    uint64_t A1l = make_desc64(a + TPAIR + TILE_B);
                    uint64_t Bh  = make_desc64(a + 2 * TPAIR);
                    uint64_t Bl  = make_desc64(a + 2 * TPAIR + TILE_B);
                    uint64_t t0a[3] = {A0h, A0l, A0h};
                    uint64_t t1a[3] = {A1h, A1l, A1h};
                    uint64_t tb[3]  = {Bh,  Bh,  Bl};
#pragma unroll
                    for (int t = 0; t < 3; ++t)
#pragma unroll
                        for (int ks = 0; ks < 2; ++ks) {
                            uint32_t en = !(sub == 0 && t == 0 && ks == 0);
                            mma_ss(d0, t0a[t] + ks * 2, tb[t] + ks * 2, en);
                            mma_ss(d1, t1a[t] + ks * 2, tb[t] + ks * 2, en);
                        }
                    // stage free (in BOTH cluster CTAs) when these MMAs drain
                    tc_commit_mcast(smem_u32(&s_empty[st]), CL_MASK);
                    st = (st + 1) & (NSTAGE - 1);
                }
                tc_commit(smem_u32(&s_mma_done[slot])); // chunk D ready (local)
            }
        }
    } else {
        // ---- epilogue: 16 warps; wid = msub*8 + grp*4 + sp ----
        const int msub = wid >> 3;
        const int grp  = (wid >> 2) & 1;
        const int sp   = wid & 3;
        float racc[64];
#pragma unroll
        for (int i = 0; i < 64; ++i) racc[i] = 0.0f;

        int mph[2] = {0, 0};
        for (int c = 0; c < NCHUNK; ++c) {
            int slot = c & 1;
            mbar_wait(smem_u32(&s_mma_done[slot]), mph[slot]); mph[slot] ^= 1;
            tc_fence_after();
            uint32_t base = tmem + (slot * 2 + msub) * 128 + grp * 64;
#pragma unroll
            for (int b = 0; b < 4; ++b) {
                uint32_t dr[16];
                ldtm16(dr, base + b * 16);
                tc_wait_ld();
#pragma unroll
                for (int j = 0; j < 16; ++j)
                    racc[b * 16 + j] += quantize_partial(__uint_as_float(dr[j]));
            }
            tc_fence_before();
            mbar_arrive(smem_u32(&s_epi_done[slot]));
        }

        const int m  = m0 + msub * 128 + sp * 32 + lane;
        const float* bp = bias + n0 + grp * 64;
        float* op = out + (size_t)m * N_DIM + n0 + grp * 64;
#pragma unroll
        for (int q = 0; q < 16; ++q) {
            float4 bb = *(const float4*)(bp + q * 4);
            float4 o;
            o.x = racc[q * 4 + 0] + bb.x;
            o.y = racc[q * 4 + 1] + bb.y;
            o.z = racc[q * 4 + 2] + bb.z;
            o.w = racc[q * 4 + 3] + bb.w;
            *(float4*)(op + q * 4) = o;
        }
    }

    __syncthreads();
    if (wid == MMA_WARP) {
        asm volatile("tcgen05.relinquish_alloc_permit.cta_group::1.sync.aligned;");
        asm volatile("tcgen05.dealloc.cta_group::1.sync.aligned.b32 %0, %1;"
                     :: "r"(tmem), "r"(512u));
    }
    cluster_sync_all();               // no exit while peer multicast in flight
#else
    // ======================= FFMA2 fallback (plain sm_103; never runs) =======
    float* As = (float*)dyn;
    float* Bs = As + 2 * 16 * 128;
#define ASF(b, k, r) As[((b) * 16 + (k)) * 128 + (r)]
#define BSF(b, k, r) Bs[((b) * 16 + (k)) * 128 + (r)]

    const int tid = threadIdx.x;
    const bool act = tid < 256;
    const int tx  = tid & 15;
    const int ty  = (tid >> 4) & 15;
    const int n0  = blockIdx.x * BN;
    const int ldr = (tid >> 2) & 63;
    const int ldq = tid & 3;

    for (int msub = 0; msub < 2; ++msub) {
        const int m0 = (blockIdx.y * 2 + msub) * 128;
        const float* ax = x + (size_t)(m0 + ldr) * K_DIM + ldq * 4;
        const float* bx = w + (size_t)(n0 + ldr) * K_DIM + ldq * 4;

        unsigned long long pacc[4][8];
        float racc[8][8];
#pragma unroll
        for (int i = 0; i < 4; ++i)
#pragma unroll
            for (int j = 0; j < 8; ++j) pacc[i][j] = 0ULL;
#pragma unroll
        for (int i = 0; i < 8; ++i)
#pragma unroll
            for (int j = 0; j < 8; ++j) racc[i][j] = 0.0f;

        __syncthreads();
        if (act) {
            float4 a0 = *(const float4*)(ax);
            float4 a1 = *(const float4*)(ax + (size_t)64 * K_DIM);
            float4 b0 = *(const float4*)(bx);
            float4 b1 = *(const float4*)(bx + (size_t)64 * K_DIM);
            ASF(0, ldq * 4 + 0, ldr) = a0.x;  ASF(0, ldq * 4 + 1, ldr) = a0.y;
            ASF(0, ldq * 4 + 2, ldr) = a0.z;  ASF(0, ldq * 4 + 3, ldr) = a0.w;
            ASF(0, ldq * 4 + 0, ldr + 64) = a1.x;  ASF(0, ldq * 4 + 1, ldr + 64) = a1.y;
            ASF(0, ldq * 4 + 2, ldr + 64) = a1.z;  ASF(0, ldq * 4 + 3, ldr + 64) = a1.w;
            BSF(0, ldq * 4 + 0, ldr) = b0.x;  BSF(0, ldq * 4 + 1, ldr) = b0.y;
            BSF(0, ldq * 4 + 2, ldr) = b0.z;  BSF(0, ldq * 4 + 3, ldr) = b0.w;
            BSF(0, ldq * 4 + 0, ldr + 64) = b1.x;  BSF(0, ldq * 4 + 1, ldr + 64) = b1.y;
            BSF(0, ldq * 4 + 2, ldr + 64) = b1.z;  BSF(0, ldq * 4 + 3, ldr + 64) = b1.w;
        }
        __syncthreads();

        int buf = 0;
        const int NSUB_F = K_DIM / 16;
        for (int s = 0; s < NSUB_F; ++s) {
            float4 a0, a1, b0, b1;
            const bool has_next = (s + 1 < NSUB_F);
            if (act && has_next) {
                const float* ap = ax + (size_t)(s + 1) * 16;
                const float* bp = bx + (size_t)(s + 1) * 16;
                a0 = *(const float4*)(ap);
                a1 = *(const float4*)(ap + (size_t)64 * K_DIM);
                b0 = *(const float4*)(bp);
                b1 = *(const float4*)(bp + (size_t)64 * K_DIM);
            }
            if (act) {
#pragma unroll
                for (int kk = 0; kk < 16; ++kk) {
                    ulonglong2 av0 = *(const ulonglong2*)&ASF(buf, kk, ty * 8);
                    ulonglong2 av1 = *(const ulonglong2*)&ASF(buf, kk, ty * 8 + 4);
                    float4 bv0 = *(const float4*)&BSF(buf, kk, tx * 8);
                    float4 bv1 = *(const float4*)&BSF(buf, kk, tx * 8 + 4);
                    unsigned long long am[4] = {av0.x, av0.y, av1.x, av1.y};
                    unsigned long long bd[8] = {dup2(bv0.x), dup2(bv0.y), dup2(bv0.z), dup2(bv0.w),
                                                dup2(bv1.x), dup2(bv1.y), dup2(bv1.z), dup2(bv1.w)};
#pragma unroll
                    for (int mi = 0; mi < 4; ++mi)
#pragma unroll
                        for (int j = 0; j < 8; ++j)
                            ffma2(pacc[mi][j], am[mi], bd[j]);
                }
                if ((s & 7) == 7) {
#pragma unroll
                    for (int mi = 0; mi < 4; ++mi)
#pragma unroll
                        for (int j = 0; j < 8; ++j) {
                            float2 p = unpack2(pacc[mi][j]);
                            racc[2 * mi + 0][j] += quantize_partial(p.x);
                            racc[2 * mi + 1][j] += quantize_partial(p.y);
                            pacc[mi][j] = 0ULL;
                        }
                }
            }
            if (has_next) {
                const int nb = buf ^ 1;
                if (act) {
                    ASF(nb, ldq * 4 + 0, ldr) = a0.x;  ASF(nb, ldq * 4 + 1, ldr) = a0.y;
                    ASF(nb, ldq * 4 + 2, ldr) = a0.z;  ASF(nb, ldq * 4 + 3, ldr) = a0.w;
                    ASF(nb, ldq * 4 + 0, ldr + 64) = a1.x;  ASF(nb, ldq * 4 + 1, ldr + 64) = a1.y;
                    ASF(nb, ldq * 4 + 2, ldr + 64) = a1.z;  ASF(nb, ldq * 4 + 3, ldr + 64) = a1.w;
                    BSF(nb, ldq * 4 + 0, ldr) = b0.x;  BSF(nb, ldq * 4 + 1, ldr) = b0.y;
                    BSF(nb, ldq * 4 + 2, ldr) = b0.z;  BSF(nb, ldq * 4 + 3, ldr) = b0.w;
                    BSF(nb, ldq * 4 + 0, ldr + 64) = b1.x;  BSF(nb, ldq * 4 + 1, ldr + 64) = b1.y;
                    BSF(nb, ldq * 4 + 2, ldr + 64) = b1.z;  BSF(nb, ldq * 4 + 3, ldr + 64) = b1.w;
                }
                __syncthreads();
                buf = nb;
            }
        }

        if (act) {
            const float* bptr = bias + n0 + tx * 8;
            float4 bb0 = *(const float4*)(bptr);
            float4 bb1 = *(const float4*)(bptr + 4);
#pragma unroll
            for (int r = 0; r < 8; ++r) {
                float* op = out + (size_t)(m0 + ty * 8 + r) * N_DIM + n0 + tx * 8;
                float4 o0, o1;
                o0.x = racc[r][0] + bb0.x;  o0.y = racc[r][1] + bb0.y;
                o0.z = racc[r][2] + bb0.z;  o0.w = racc[r][3] + bb0.w;
                o1.x = racc[r][4] + bb1.x;  o1.y = racc[r][5] + bb1.y;
                o1.z = racc[r][6] + bb1.z;  o1.w = racc[r][7] + bb1.w;
                *(float4*)(op)     = o0;
                *(float4*)(op + 4) = o1;
            }
        }
    }
#undef ASF
#undef BSF
#endif
}

// ---------------------------------------------------------------------------
extern "C" void kernel_launch(void* const* d_in, const int* in_sizes, int n_in,
                              void* d_out, int out_size) {
    const float* x    = (const float*)d_in[0];
    const float* w    = (const float*)d_in[1];
    const float* bias = (const float*)d_in[2];
    float* out = (float*)d_out;

    const int Bdim = in_sizes[0] / K_DIM;   // 8192

    uint8_t* xpack = nullptr; uint8_t* wpack = nullptr;
    cudaGetSymbolAddress((void**)&xpack, g_xpack);
    cudaGetSymbolAddress((void**)&wpack, g_wpack);

    cudaFuncSetAttribute(vmm_main_kernel,
                         cudaFuncAttributeMaxDynamicSharedMemorySize, DYN_BYTES);

    pack_kernel<<<Bdim * 2, 256>>>(x, xpack, Bdim);
    pack_kernel<<<N_DIM * 2, 256>>>(w, wpack, N_DIM);

    dim3 grid(N_DIM / BN, Bdim / BM);       // (32, 32)
    vmm_main_kernel<<<grid, THREADS, DYN_BYTES>>>(x, w, bias, out);
}